// round 1
// baseline (speedup 1.0000x reference)
#include <cuda_runtime.h>

#define N_ 8
#define C_ 64
#define L_ 512
#define D_ 64
#define TI 16   // rows of i per block in band kernel
#define BW 64   // band width

// scratch (static device globals — no allocation)
__device__ float g_qb[N_ * L_ * D_];  // q + bh
__device__ float g_kk[N_ * L_ * D_];  // k

// ---------------------------------------------------------------------------
// FMA/ALU-only tanh: abs error ~1e-6, zero MUFU usage.
// tanh(|x|) = 1 - 2/(1 + 2^(|x| * 2*log2(e))); sign restored by bit OR.
// ---------------------------------------------------------------------------
__device__ __forceinline__ float tanh_fast(float x) {
    float ax = fabsf(x);
    float z  = fminf(ax * 2.885390081777927f, 24.0f);   // 2*log2(e)*|x|, clamped
    float zr = z + 12582912.0f;                          // 1.5*2^23 round trick
    int   ik = __float_as_int(zr) - 0x4B400000;          // round(z) as int
    float f  = z - (zr - 12582912.0f);                   // frac in [-0.5, 0.5]
    float sc = __int_as_float((ik + 127) << 23);         // 2^round(z)
    // 2^f, Taylor degree 6 (rel err ~2e-7 on [-0.5,0.5])
    float p = 1.5403530394e-4f;
    p = fmaf(p, f, 1.3333558146e-3f);
    p = fmaf(p, f, 9.6181291076e-3f);
    p = fmaf(p, f, 5.5504108665e-2f);
    p = fmaf(p, f, 2.4022650696e-1f);
    p = fmaf(p, f, 6.9314718056e-1f);
    p = fmaf(p, f, 1.0f);
    float e   = p * sc;            // e^{2|x|} in [1, ~2^24]
    float den = e + 1.0f;
    // reciprocal: magic guess + 3 Newton iterations (quadratic convergence)
    float y = __int_as_float(0x7EF311C3 - __float_as_int(den));
    y = y * fmaf(-den, y, 2.0f);
    y = y * fmaf(-den, y, 2.0f);
    y = y * fmaf(-den, y, 2.0f);
    float t = fmaf(-2.0f, y, 1.0f);                      // tanh(|x|) >= 0
    return __int_as_float(__float_as_int(t) | (__float_as_int(x) & 0x80000000));
}

// ---------------------------------------------------------------------------
// Kernel 1: q = xt@Wt + bh, k = xt@Wx   (xt[l,c] = x[n,c,l])
// grid (N_, L_/32), 256 threads
// ---------------------------------------------------------------------------
__global__ void proj_kernel(const float* __restrict__ x,
                            const float* __restrict__ Wx,
                            const float* __restrict__ Wt,
                            const float* __restrict__ bh) {
    __shared__ float xs[C_][33];
    __shared__ float wt[C_][D_];
    __shared__ float wx[C_][D_];
    int n  = blockIdx.x;
    int l0 = blockIdx.y * 32;
    int t  = threadIdx.x;

    for (int idx = t; idx < C_ * D_; idx += 256) {
        wt[idx >> 6][idx & 63] = Wt[idx];
        wx[idx >> 6][idx & 63] = Wx[idx];
    }
    for (int idx = t; idx < C_ * 32; idx += 256) {
        int c = idx >> 5, ll = idx & 31;
        xs[c][ll] = x[(n * C_ + c) * L_ + l0 + ll];
    }
    __syncthreads();

    for (int p = t; p < 32 * D_; p += 256) {
        int ll = p >> 6, d = p & 63;
        float aq = 0.f, ak = 0.f;
#pragma unroll
        for (int c = 0; c < C_; c++) {
            float xv = xs[c][ll];
            aq = fmaf(xv, wt[c][d], aq);
            ak = fmaf(xv, wx[c][d], ak);
        }
        int gi = (n * L_ + l0 + ll) * D_ + d;
        g_qb[gi] = aq + bh[d];
        g_kk[gi] = ak;
    }
}

// ---------------------------------------------------------------------------
// Kernel 2: banded scores + softmax + a-write + v = a@xt
// grid (N_, L_/TI), 512 threads = 16 warps, one warp per row i
// ---------------------------------------------------------------------------
__global__ void __launch_bounds__(512)
band_kernel(const float* __restrict__ x,
            const float* __restrict__ Wa,
            float* __restrict__ out) {
    __shared__ float ks[TI + 63][65];   // k band tile, pitch 65 (conflict-free)
    __shared__ float xb[C_][81];        // x band tile, pitch 81 (conflict-free)
    __shared__ float qa[TI][64];        // q rows, later reused as a rows
    __shared__ float wa_s[D_];

    int n     = blockIdx.x;
    int i0    = blockIdx.y * TI;
    int t     = threadIdx.x;
    int jbase = i0 - 32;                // leftmost band column for this tile

    for (int idx = t; idx < (TI + 63) * D_; idx += 512) {
        int jj = idx >> 6, d = idx & 63;
        int gj = jbase + jj;
        ks[jj][d] = ((unsigned)gj < (unsigned)L_) ? g_kk[(n * L_ + gj) * D_ + d] : 0.f;
    }
    for (int idx = t; idx < C_ * (TI + 63); idx += 512) {
        int c = idx / (TI + 63), col = idx % (TI + 63);
        int gj = jbase + col;
        xb[c][col] = ((unsigned)gj < (unsigned)L_) ? x[(n * C_ + c) * L_ + gj] : 0.f;
    }
    for (int idx = t; idx < TI * D_; idx += 512) {
        qa[idx >> 6][idx & 63] = g_qb[(n * L_ + i0 + (idx >> 6)) * D_ + (idx & 63)];
    }
    if (t < D_) wa_s[t] = Wa[t];
    __syncthreads();

    int w  = t >> 5;
    int ln = t & 31;
    int i  = i0 + w;
    int col0 = w + ln;        // tile column for band offset jl = ln
    int col1 = col0 + 32;     // tile column for band offset jl = ln + 32

    // --- scores: each lane computes 2 of the 64 band entries of row i ---
    float acc0 = 0.f, acc1 = 0.f;
#pragma unroll 4
    for (int d = 0; d < D_; d++) {
        float qv = qa[w][d];
        float wv = wa_s[d];
        float t0 = tanh_fast(qv + ks[col0][d]);
        float t1 = tanh_fast(qv + ks[col1][d]);
        acc0 = fmaf(t0, wv, acc0);
        acc1 = fmaf(t1, wv, acc1);
    }

    int gj0 = jbase + col0;
    int gj1 = jbase + col1;
    bool v0 = (unsigned)gj0 < (unsigned)L_;
    bool v1 = (unsigned)gj1 < (unsigned)L_;

    // --- band softmax (max over band; eps-effect of full-row max is <1e-4) ---
    float s0 = v0 ? acc0 : -1e30f;
    float s1 = v1 ? acc1 : -1e30f;
    float m  = fmaxf(s0, s1);
#pragma unroll
    for (int o = 16; o > 0; o >>= 1) m = fmaxf(m, __shfl_xor_sync(0xffffffffu, m, o));
    float e0 = v0 ? __expf(acc0 - m) : 0.f;
    float e1 = v1 ? __expf(acc1 - m) : 0.f;
    float s  = e0 + e1;
#pragma unroll
    for (int o = 16; o > 0; o >>= 1) s += __shfl_xor_sync(0xffffffffu, s, o);
    float rinv = __fdividef(1.f, s + 1e-6f);
    float a0 = e0 * rinv;
    float a1 = e1 * rinv;

    __syncwarp();
    qa[w][ln]      = a0;   // q row no longer needed: reuse as a row
    qa[w][ln + 32] = a1;
    __syncwarp();

    // --- write full a row (zeros outside band; covers poisoned output) ---
    float* arow = out + (size_t)N_ * C_ * L_ + ((size_t)(n * L_ + i)) * L_;
#pragma unroll
    for (int idx = ln; idx < L_; idx += 32) {
        int jl = idx - (i - 32);
        arow[idx] = ((unsigned)jl < 64u) ? qa[w][jl] : 0.f;
    }

    // --- v[n, c, i] = sum_j a[i,j] * x[n, c, j], lane handles c=ln, ln+32 ---
    float vacc0 = 0.f, vacc1 = 0.f;
#pragma unroll 8
    for (int jl = 0; jl < BW; jl++) {
        float av = qa[w][jl];
        vacc0 = fmaf(av, xb[ln][w + jl], vacc0);
        vacc1 = fmaf(av, xb[ln + 32][w + jl], vacc1);
    }
    out[(n * C_ + ln) * L_ + i]      = vacc0;
    out[(n * C_ + ln + 32) * L_ + i] = vacc1;
}

// ---------------------------------------------------------------------------
extern "C" void kernel_launch(void* const* d_in, const int* in_sizes, int n_in,
                              void* d_out, int out_size) {
    const float* x  = (const float*)d_in[0];
    const float* Wx = (const float*)d_in[1];
    const float* Wt = (const float*)d_in[2];
    const float* bh = (const float*)d_in[3];
    const float* Wa = (const float*)d_in[4];
    // d_in[5] = ba: cancels inside exp(e - max), unused.
    float* out = (float*)d_out;

    proj_kernel<<<dim3(N_, L_ / 32), 256>>>(x, Wx, Wt, bh);
    band_kernel<<<dim3(N_, L_ / TI), 512>>>(x, Wa, out);
}

// round 4
// speedup vs baseline: 1.1662x; 1.1662x over previous
#include <cuda_runtime.h>

#define N_ 8
#define C_ 64
#define L_ 512
#define D_ 64
#define TI 8     // rows of i per band block
#define SC 2.885390081777927f   // 2*log2(e): prescale so q+k is already the exp2 arg

// scratch (static device globals — no allocation); 16B-aligned for float4 access
__device__ __align__(16) float g_qb[N_ * L_ * D_];  // (q + bh) * SC
__device__ __align__(16) float g_kk[N_ * L_ * D_];  // k * SC

// ---------------------------------------------------------------------------
// FMA/ALU-only tanh from prescaled input z0 = 2*log2(e)*x.
// tanh(x) = 1 - 2/(1 + 2^z0). Valid for all signs, ~1e-6 abs err.
// ---------------------------------------------------------------------------
__device__ __forceinline__ float tanh_fast(float z0) {
    float z  = fminf(fmaxf(z0, -24.0f), 24.0f);
    float zr = z + 12582912.0f;                  // 1.5*2^23 round trick
    float f  = z - (zr - 12582912.0f);           // frac in [-0.5, 0.5]
    float sc = __int_as_float((__float_as_int(zr) << 23) + 0x3F800000); // 2^round(z)
    float p = 1.3333558146e-3f;                  // 2^f Taylor deg-5 (rel err ~2e-6)
    p = fmaf(p, f, 9.6181291076e-3f);
    p = fmaf(p, f, 5.5504108665e-2f);
    p = fmaf(p, f, 2.4022650696e-1f);
    p = fmaf(p, f, 6.9314718056e-1f);
    p = fmaf(p, f, 1.0f);
    float den = fmaf(p, sc, 1.0f);               // e^{2x} + 1 in one FMA
    float y = __int_as_float(0x7EF311C3 - __float_as_int(den));  // rcp guess
    y = y * fmaf(-den, y, 2.0f);                 // Newton 1
    y = y * fmaf(-den, y, 2.0f);                 // Newton 2 (rel err ~1.3e-6)
    return fmaf(-2.0f, y, 1.0f);
}

// ---------------------------------------------------------------------------
// Kernel 1: q' = (xt@Wt + bh)*SC, k' = (xt@Wx)*SC
// grid (N_, L_/16), 256 threads; register-blocked 4 d per thread, float4 LDS
// ---------------------------------------------------------------------------
__global__ void __launch_bounds__(256)
proj_kernel(const float* __restrict__ x,
            const float* __restrict__ Wx,
            const float* __restrict__ Wt,
            const float* __restrict__ bh) {
    __shared__ __align__(16) float wt[C_ * D_];
    __shared__ __align__(16) float wx[C_ * D_];
    __shared__ float xs[C_][17];
    int n  = blockIdx.x;
    int l0 = blockIdx.y * 16;
    int t  = threadIdx.x;

    for (int i4 = t; i4 < C_ * D_ / 4; i4 += 256) {
        ((float4*)wt)[i4] = ((const float4*)Wt)[i4];
        ((float4*)wx)[i4] = ((const float4*)Wx)[i4];
    }
    for (int idx = t; idx < C_ * 16; idx += 256) {
        int c = idx >> 4, ll = idx & 15;
        xs[c][ll] = x[(n * C_ + c) * L_ + l0 + ll];
    }
    __syncthreads();

    int dg = t & 15, ll = t >> 4;
    int d0 = dg << 2;
    float q0 = 0, q1 = 0, q2 = 0, q3 = 0, k0 = 0, k1 = 0, k2 = 0, k3 = 0;
#pragma unroll 8
    for (int c = 0; c < C_; c++) {
        float  xv  = xs[c][ll];
        float4 wt4 = *(const float4*)(wt + c * D_ + d0);
        float4 wx4 = *(const float4*)(wx + c * D_ + d0);
        q0 = fmaf(xv, wt4.x, q0); q1 = fmaf(xv, wt4.y, q1);
        q2 = fmaf(xv, wt4.z, q2); q3 = fmaf(xv, wt4.w, q3);
        k0 = fmaf(xv, wx4.x, k0); k1 = fmaf(xv, wx4.y, k1);
        k2 = fmaf(xv, wx4.z, k2); k3 = fmaf(xv, wx4.w, k3);
    }
    float4 b4 = *(const float4*)(bh + d0);
    int gi = (n * L_ + l0 + ll) * D_ + d0;
    float4 qo = { (q0 + b4.x) * SC, (q1 + b4.y) * SC, (q2 + b4.z) * SC, (q3 + b4.w) * SC };
    float4 ko = { k0 * SC, k1 * SC, k2 * SC, k3 * SC };
    *(float4*)(g_qb + gi) = qo;
    *(float4*)(g_kk + gi) = ko;
}

// ---------------------------------------------------------------------------
// Kernel 2: banded scores + softmax + a + v. 2 warps per row (one per half-band).
// grid (N_, L_/TI) = 512 blocks, 512 threads = 16 warps.
// ---------------------------------------------------------------------------
__global__ void __launch_bounds__(512)
band_kernel(const float* __restrict__ x,
            const float* __restrict__ Wa,
            float* __restrict__ out) {
    __shared__ float ks[TI + 63][65];            // k' band tile, pitch 65
    __shared__ float xb[C_][71];                 // x band tile, pitch 71
    __shared__ __align__(16) float qa[TI][64];   // q' rows; reused as a rows
    __shared__ float wa_s[D_];
    __shared__ float red_m[TI][2], red_s[TI][2];
    __shared__ float v_s[C_][9];                 // v transpose staging

    int n     = blockIdx.x;
    int i0    = blockIdx.y * TI;
    int t     = threadIdx.x;
    int jbase = i0 - 32;

    // --- stage tiles ---
    for (int i4 = t; i4 < (TI + 63) * 16; i4 += 512) {   // k band, float4 loads
        int jj = i4 >> 4, d4 = (i4 & 15) << 2;
        int gj = jbase + jj;
        if ((unsigned)gj < (unsigned)L_) {
            float4 v = *(const float4*)(g_kk + ((n * L_ + gj) << 6) + d4);
            ks[jj][d4] = v.x; ks[jj][d4 + 1] = v.y; ks[jj][d4 + 2] = v.z; ks[jj][d4 + 3] = v.w;
        } else {
            ks[jj][d4] = 0.f; ks[jj][d4 + 1] = 0.f; ks[jj][d4 + 2] = 0.f; ks[jj][d4 + 3] = 0.f;
        }
    }
    for (int idx = t; idx < C_ * 71; idx += 512) {
        int c = idx / 71, col = idx - c * 71;
        int gj = jbase + col;
        xb[c][col] = ((unsigned)gj < (unsigned)L_) ? x[(n * C_ + c) * L_ + gj] : 0.f;
    }
    if (t < 128) ((float4*)qa)[t] = ((const float4*)(g_qb + (n * L_ + i0) * D_))[t];
    if (t < D_)  wa_s[t] = Wa[t];
    __syncthreads();

    int w = t >> 5, ln = t & 31;
    int w_row = w >> 1, h = w & 1;      // 2 warps per row: h = half-band
    int i   = i0 + w_row;
    int jl  = h * 32 + ln;              // band offset 0..63 (1 per lane)
    int col = w_row + jl;               // tile column
    int gj  = jbase + col;
    bool valid = (unsigned)gj < (unsigned)L_;

    // --- score for this lane's band entry ---
    float acc = 0.f;
#pragma unroll 4
    for (int d = 0; d < D_; d++) {
        float z = qa[w_row][d] + ks[col][d];      // already the exp2 argument
        acc = fmaf(tanh_fast(z), wa_s[d], acc);
    }

    // --- band softmax across 64 entries = 2 warps ---
    float m = valid ? acc : -1e30f;
#pragma unroll
    for (int o = 16; o > 0; o >>= 1) m = fmaxf(m, __shfl_xor_sync(0xffffffffu, m, o));
    if (ln == 0) red_m[w_row][h] = m;
    __syncthreads();
    float M = fmaxf(red_m[w_row][0], red_m[w_row][1]);
    float e = valid ? __expf(acc - M) : 0.f;
    float s = e;
#pragma unroll
    for (int o = 16; o > 0; o >>= 1) s += __shfl_xor_sync(0xffffffffu, s, o);
    if (ln == 0) red_s[w_row][h] = s;
    __syncthreads();
    float S = red_s[w_row][0] + red_s[w_row][1];
    float a = e * __fdividef(1.f, S + 1e-6f);
    qa[w_row][jl] = a;                  // q row dead: reuse as a row
    __syncthreads();

    // --- v[n, c, i]: lane handles c = jl (= h*32+ln) ---
    int c = jl;
    float vacc = 0.f;
#pragma unroll 8
    for (int j2 = 0; j2 < 64; j2++)
        vacc = fmaf(qa[w_row][j2], xb[c][w_row + j2], vacc);
    v_s[c][w_row] = vacc;

    // --- full a row, STG.128 (zeros outside band cover the poisoned output) ---
    float* arow = out + (size_t)N_ * C_ * L_ + (size_t)(n * L_ + i) * L_;
#pragma unroll
    for (int k = 0; k < 2; k++) {
        int idx = (h * 64 + k * 32 + ln) << 2;    // float index, multiple of 4
        int j0  = idx - i + 32;
        float4 vv;
        vv.x = ((unsigned)(j0)     < 64u) ? qa[w_row][j0]     : 0.f;
        vv.y = ((unsigned)(j0 + 1) < 64u) ? qa[w_row][j0 + 1] : 0.f;
        vv.z = ((unsigned)(j0 + 2) < 64u) ? qa[w_row][j0 + 2] : 0.f;
        vv.w = ((unsigned)(j0 + 3) < 64u) ? qa[w_row][j0 + 3] : 0.f;
        *(float4*)(arow + idx) = vv;
    }
    __syncthreads();

    // --- coalesced v store via transpose staging ---
    int c2 = t >> 3, il = t & 7;
    out[(n * C_ + c2) * L_ + i0 + il] = v_s[c2][il];
}

// ---------------------------------------------------------------------------
extern "C" void kernel_launch(void* const* d_in, const int* in_sizes, int n_in,
                              void* d_out, int out_size) {
    const float* x  = (const float*)d_in[0];
    const float* Wx = (const float*)d_in[1];
    const float* Wt = (const float*)d_in[2];
    const float* bh = (const float*)d_in[3];
    const float* Wa = (const float*)d_in[4];
    // d_in[5] = ba: cancels inside exp(e - max), unused.
    float* out = (float*)d_out;

    proj_kernel<<<dim3(N_, L_ / 16), 256>>>(x, Wx, Wt, bh);
    band_kernel<<<dim3(N_, L_ / TI), 512>>>(x, Wa, out);
}

// round 6
// speedup vs baseline: 1.3120x; 1.1250x over previous
#include <cuda_runtime.h>

#define N_ 8
#define C_ 64
#define L_ 512
#define D_ 64
#define TI 8     // rows of i per band block
#define SC 2.885390081777927f   // 2*log2(e): prescale so q+k is already the exp2 arg
#define KP 68    // ks smem pitch: multiple of 4 (16B align) and conflict-free

// scratch (static device globals — no allocation); 16B-aligned for float4 access
__device__ __align__(16) float g_qb[N_ * L_ * D_];  // (q + bh) * SC
__device__ __align__(16) float g_kk[N_ * L_ * D_];  // k * SC

// ---------------------------------------------------------------------------
// MUFU exp2 / rcp via inline asm (no fast-math dependence), plus an fma-pipe
// Newton reciprocal. MUFU and fma versions alternated per d to balance pipes.
// ---------------------------------------------------------------------------
__device__ __forceinline__ float ex2_m(float z) {
    float y;
    asm("ex2.approx.f32 %0, %1;" : "=f"(y) : "f"(z));
    return y;
}
__device__ __forceinline__ float rcp_m(float den) {
    float y;
    asm("rcp.approx.f32 %0, %1;" : "=f"(y) : "f"(den));
    return y;
}
__device__ __forceinline__ float rcp_n(float den) {
    float y = __int_as_float(0x7EF311C3 - __float_as_int(den));
    y = y * fmaf(-den, y, 2.0f);
    y = y * fmaf(-den, y, 2.0f);
    return y;
}
// y = 1/(2^z + 1); tanh(x) = 1 - 2y; score accumulates wa*(1-2y) -> const + (-2wa)*y
__device__ __forceinline__ float sig_m(float z) { return rcp_m(ex2_m(z) + 1.0f); }
__device__ __forceinline__ float sig_n(float z) { return rcp_n(ex2_m(z) + 1.0f); }

// ---------------------------------------------------------------------------
// Kernel 1: q' = (xt@Wt + bh)*SC, k' = (xt@Wx)*SC
// ---------------------------------------------------------------------------
__global__ void __launch_bounds__(256)
proj_kernel(const float* __restrict__ x,
            const float* __restrict__ Wx,
            const float* __restrict__ Wt,
            const float* __restrict__ bh) {
    __shared__ __align__(16) float wt[C_ * D_];
    __shared__ __align__(16) float wx[C_ * D_];
    __shared__ float xs[C_][17];
    int n  = blockIdx.x;
    int l0 = blockIdx.y * 16;
    int t  = threadIdx.x;

    for (int i4 = t; i4 < C_ * D_ / 4; i4 += 256) {
        ((float4*)wt)[i4] = ((const float4*)Wt)[i4];
        ((float4*)wx)[i4] = ((const float4*)Wx)[i4];
    }
    for (int idx = t; idx < C_ * 16; idx += 256) {
        int c = idx >> 4, ll = idx & 15;
        xs[c][ll] = x[(n * C_ + c) * L_ + l0 + ll];
    }
    __syncthreads();

    int dg = t & 15, ll = t >> 4;
    int d0 = dg << 2;
    float q0 = 0, q1 = 0, q2 = 0, q3 = 0, k0 = 0, k1 = 0, k2 = 0, k3 = 0;
#pragma unroll 8
    for (int c = 0; c < C_; c++) {
        float  xv  = xs[c][ll];
        float4 wt4 = *(const float4*)(wt + c * D_ + d0);
        float4 wx4 = *(const float4*)(wx + c * D_ + d0);
        q0 = fmaf(xv, wt4.x, q0); q1 = fmaf(xv, wt4.y, q1);
        q2 = fmaf(xv, wt4.z, q2); q3 = fmaf(xv, wt4.w, q3);
        k0 = fmaf(xv, wx4.x, k0); k1 = fmaf(xv, wx4.y, k1);
        k2 = fmaf(xv, wx4.z, k2); k3 = fmaf(xv, wx4.w, k3);
    }
    float4 b4 = *(const float4*)(bh + d0);
    int gi = (n * L_ + l0 + ll) * D_ + d0;
    float4 qo = { (q0 + b4.x) * SC, (q1 + b4.y) * SC, (q2 + b4.z) * SC, (q3 + b4.w) * SC };
    float4 ko = { k0 * SC, k1 * SC, k2 * SC, k3 * SC };
    *(float4*)(g_qb + gi) = qo;
    *(float4*)(g_kk + gi) = ko;
}

// ---------------------------------------------------------------------------
// Kernel 2: banded scores + softmax + a + v. 2 warps per row (one per half-band).
// grid (N_, L_/TI) = 512 blocks, 512 threads = 16 warps.
// ---------------------------------------------------------------------------
__global__ void __launch_bounds__(512)
band_kernel(const float* __restrict__ x,
            const float* __restrict__ Wa,
            float* __restrict__ out) {
    __shared__ __align__(16) float ks[TI + 63][KP];  // k' band tile
    __shared__ float xb[C_][71];                     // x band tile (pitch 71)
    __shared__ __align__(16) float qa[TI][64];       // q' rows; reused as a rows
    __shared__ __align__(16) float wa2_s[D_];        // -2 * Wa
    __shared__ float red_m[TI][2], red_s[TI][2];
    __shared__ float v_s[C_][9];                     // v transpose staging

    int n     = blockIdx.x;
    int i0    = blockIdx.y * TI;
    int t     = threadIdx.x;
    int jbase = i0 - 32;

    // --- stage tiles ---
    for (int i4 = t; i4 < (TI + 63) * 16; i4 += 512) {   // k band, float4
        int jj = i4 >> 4, d4 = (i4 & 15) << 2;
        int gj = jbase + jj;
        float4 v = { 0.f, 0.f, 0.f, 0.f };
        if ((unsigned)gj < (unsigned)L_)
            v = *(const float4*)(g_kk + ((n * L_ + gj) << 6) + d4);
        *(float4*)&ks[jj][d4] = v;
    }
    for (int idx = t; idx < C_ * 71; idx += 512) {
        int c = idx / 71, col = idx - c * 71;
        int gj = jbase + col;
        xb[c][col] = ((unsigned)gj < (unsigned)L_) ? x[(n * C_ + c) * L_ + gj] : 0.f;
    }
    if (t < 128) ((float4*)qa)[t] = ((const float4*)(g_qb + (n * L_ + i0) * D_))[t];
    if (t < D_)  wa2_s[t] = -2.0f * Wa[t];
    __syncthreads();

    int w = t >> 5, ln = t & 31;
    int w_row = w >> 1, h = w & 1;      // 2 warps per row: h = half-band
    int i   = i0 + w_row;
    int jl  = h * 32 + ln;              // band offset 0..63 (1 per lane)
    int col = w_row + jl;               // tile column
    int gj  = jbase + col;
    bool valid = (unsigned)gj < (unsigned)L_;

    // --- score (up to a constant, which cancels in softmax):
    //     acc = sum_d (-2 wa_d) / (1 + 2^(q'_d + k'_d))
    float acc = 0.f;
#pragma unroll
    for (int d4 = 0; d4 < D_; d4 += 4) {
        float4 kv = *(const float4*)&ks[col][d4];
        float4 qv = *(const float4*)&qa[w_row][d4];
        float4 wv = *(const float4*)&wa2_s[d4];
        acc = fmaf(wv.x, sig_m(qv.x + kv.x), acc);   // MUFU rcp
        acc = fmaf(wv.y, sig_n(qv.y + kv.y), acc);   // Newton rcp
        acc = fmaf(wv.z, sig_m(qv.z + kv.z), acc);
        acc = fmaf(wv.w, sig_n(qv.w + kv.w), acc);
    }

    // --- band softmax across 64 entries = 2 warps ---
    float m = valid ? acc : -1e30f;
#pragma unroll
    for (int o = 16; o > 0; o >>= 1) m = fmaxf(m, __shfl_xor_sync(0xffffffffu, m, o));
    if (ln == 0) red_m[w_row][h] = m;
    __syncthreads();
    float M = fmaxf(red_m[w_row][0], red_m[w_row][1]);
    float e = valid ? ex2_m((acc - M) * 1.442695040888963f) : 0.f;
    float s = e;
#pragma unroll
    for (int o = 16; o > 0; o >>= 1) s += __shfl_xor_sync(0xffffffffu, s, o);
    if (ln == 0) red_s[w_row][h] = s;
    __syncthreads();
    float S = red_s[w_row][0] + red_s[w_row][1];
    float a = e * rcp_m(S + 1e-6f);
    qa[w_row][jl] = a;                  // q row dead: reuse as a row
    __syncthreads();

    // --- v[n, c, i]: lane handles c = jl; a via float4 broadcast ---
    int c = jl;
    float vacc = 0.f;
#pragma unroll
    for (int j4 = 0; j4 < 64; j4 += 4) {
        float4 av = *(const float4*)&qa[w_row][j4];
        vacc = fmaf(av.x, xb[c][w_row + j4],     vacc);
        vacc = fmaf(av.y, xb[c][w_row + j4 + 1], vacc);
        vacc = fmaf(av.z, xb[c][w_row + j4 + 2], vacc);
        vacc = fmaf(av.w, xb[c][w_row + j4 + 3], vacc);
    }
    v_s[c][w_row] = vacc;

    // --- full a row, STG.128 (zeros outside band cover the poisoned output) ---
    float* arow = out + (size_t)N_ * C_ * L_ + (size_t)(n * L_ + i) * L_;
#pragma unroll
    for (int k = 0; k < 2; k++) {
        int idx = (h * 64 + k * 32 + ln) << 2;    // float index, multiple of 4
        int j0  = idx - i + 32;
        float4 vv;
        vv.x = ((unsigned)(j0)     < 64u) ? qa[w_row][j0]     : 0.f;
        vv.y = ((unsigned)(j0 + 1) < 64u) ? qa[w_row][j0 + 1] : 0.f;
        vv.z = ((unsigned)(j0 + 2) < 64u) ? qa[w_row][j0 + 2] : 0.f;
        vv.w = ((unsigned)(j0 + 3) < 64u) ? qa[w_row][j0 + 3] : 0.f;
        *(float4*)(arow + idx) = vv;
    }
    __syncthreads();

    // --- coalesced v store via transpose staging ---
    int c2 = t >> 3, il = t & 7;
    out[(n * C_ + c2) * L_ + i0 + il] = v_s[c2][il];
}

// ---------------------------------------------------------------------------
extern "C" void kernel_launch(void* const* d_in, const int* in_sizes, int n_in,
                              void* d_out, int out_size) {
    const float* x  = (const float*)d_in[0];
    const float* Wx = (const float*)d_in[1];
    const float* Wt = (const float*)d_in[2];
    const float* bh = (const float*)d_in[3];
    const float* Wa = (const float*)d_in[4];
    // d_in[5] = ba: cancels inside exp(e - max), unused.
    float* out = (float*)d_out;

    proj_kernel<<<dim3(N_, L_ / 16), 256>>>(x, Wx, Wt, bh);
    band_kernel<<<dim3(N_, L_ / TI), 512>>>(x, Wa, out);
}

// round 7
// speedup vs baseline: 1.3243x; 1.0094x over previous
#include <cuda_runtime.h>

#define N_ 8
#define C_ 64
#define L_ 512
#define D_ 64
#define TI 8     // rows of i per band block
#define SC 2.885390081777927f   // 2*log2(e): prescale so q+k is already the exp2 arg
#define KP 68    // ks smem pitch: multiple of 4 (16B align) and conflict-free

// scratch (static device globals — no allocation); 16B-aligned for float4 access
__device__ __align__(16) float g_qb[N_ * L_ * D_];  // (q + bh) * SC
__device__ __align__(16) float g_kk[N_ * L_ * D_];  // k * SC

// ---------------------------------------------------------------------------
// MUFU exp2 / rcp via inline asm (no fast-math dependence).
// y = 1/(2^z + 1); tanh(x) = 1 - 2y; score = const + sum (-2wa)*y (const cancels)
// ---------------------------------------------------------------------------
__device__ __forceinline__ float ex2_m(float z) {
    float y;
    asm("ex2.approx.f32 %0, %1;" : "=f"(y) : "f"(z));
    return y;
}
__device__ __forceinline__ float rcp_m(float den) {
    float y;
    asm("rcp.approx.f32 %0, %1;" : "=f"(y) : "f"(den));
    return y;
}
__device__ __forceinline__ float sig_m(float z) { return rcp_m(ex2_m(z) + 1.0f); }

// ---------------------------------------------------------------------------
// Kernel 1: q' = (xt@Wt + bh)*SC, k' = (xt@Wx)*SC
// ---------------------------------------------------------------------------
__global__ void __launch_bounds__(256)
proj_kernel(const float* __restrict__ x,
            const float* __restrict__ Wx,
            const float* __restrict__ Wt,
            const float* __restrict__ bh) {
    __shared__ __align__(16) float wt[C_ * D_];
    __shared__ __align__(16) float wx[C_ * D_];
    __shared__ float xs[C_][17];
    int n  = blockIdx.x;
    int l0 = blockIdx.y * 16;
    int t  = threadIdx.x;

    for (int i4 = t; i4 < C_ * D_ / 4; i4 += 256) {
        ((float4*)wt)[i4] = ((const float4*)Wt)[i4];
        ((float4*)wx)[i4] = ((const float4*)Wx)[i4];
    }
    for (int idx = t; idx < C_ * 16; idx += 256) {
        int c = idx >> 4, ll = idx & 15;
        xs[c][ll] = x[(n * C_ + c) * L_ + l0 + ll];
    }
    __syncthreads();

    int dg = t & 15, ll = t >> 4;
    int d0 = dg << 2;
    float q0 = 0, q1 = 0, q2 = 0, q3 = 0, k0 = 0, k1 = 0, k2 = 0, k3 = 0;
#pragma unroll 8
    for (int c = 0; c < C_; c++) {
        float  xv  = xs[c][ll];
        float4 wt4 = *(const float4*)(wt + c * D_ + d0);
        float4 wx4 = *(const float4*)(wx + c * D_ + d0);
        q0 = fmaf(xv, wt4.x, q0); q1 = fmaf(xv, wt4.y, q1);
        q2 = fmaf(xv, wt4.z, q2); q3 = fmaf(xv, wt4.w, q3);
        k0 = fmaf(xv, wx4.x, k0); k1 = fmaf(xv, wx4.y, k1);
        k2 = fmaf(xv, wx4.z, k2); k3 = fmaf(xv, wx4.w, k3);
    }
    float4 b4 = *(const float4*)(bh + d0);
    int gi = (n * L_ + l0 + ll) * D_ + d0;
    float4 qo = { (q0 + b4.x) * SC, (q1 + b4.y) * SC, (q2 + b4.z) * SC, (q3 + b4.w) * SC };
    float4 ko = { k0 * SC, k1 * SC, k2 * SC, k3 * SC };
    *(float4*)(g_qb + gi) = qo;
    *(float4*)(g_kk + gi) = ko;
}

// ---------------------------------------------------------------------------
// Kernel 2: banded scores + softmax + a + v. 2 warps per row (one per half-band).
// grid (N_, L_/TI) = 512 blocks, 512 threads = 16 warps. 4 blocks/SM forced.
// ---------------------------------------------------------------------------
__global__ void __launch_bounds__(512, 4)
band_kernel(const float* __restrict__ x,
            const float* __restrict__ Wa,
            float* __restrict__ out) {
    __shared__ __align__(16) float ks[TI + 63][KP];  // k' band tile
    __shared__ float xb[C_][71];                     // x band tile (pitch 71)
    __shared__ __align__(16) float qa[TI][64];       // q' rows; reused as a rows
    __shared__ __align__(16) float wa2_s[D_];        // -2 * Wa
    __shared__ float red_m[TI][2], red_s[TI][2];
    __shared__ float v_s[C_][9];                     // v transpose staging

    int n     = blockIdx.x;
    int i0    = blockIdx.y * TI;
    int t     = threadIdx.x;
    int jbase = i0 - 32;

    // --- stage tiles ---
    for (int i4 = t; i4 < (TI + 63) * 16; i4 += 512) {   // k band, float4
        int jj = i4 >> 4, d4 = (i4 & 15) << 2;
        int gj = jbase + jj;
        float4 v = { 0.f, 0.f, 0.f, 0.f };
        if ((unsigned)gj < (unsigned)L_)
            v = *(const float4*)(g_kk + ((n * L_ + gj) << 6) + d4);
        *(float4*)&ks[jj][d4] = v;
    }
    for (int idx = t; idx < C_ * 71; idx += 512) {
        int c = idx / 71, col = idx - c * 71;
        int gj = jbase + col;
        xb[c][col] = ((unsigned)gj < (unsigned)L_) ? x[(n * C_ + c) * L_ + gj] : 0.f;
    }
    if (t < 128) ((float4*)qa)[t] = ((const float4*)(g_qb + (n * L_ + i0) * D_))[t];
    if (t < D_)  wa2_s[t] = -2.0f * Wa[t];
    __syncthreads();

    int w = t >> 5, ln = t & 31;
    int w_row = w >> 1, h = w & 1;      // 2 warps per row: h = half-band
    int i   = i0 + w_row;
    int jl  = h * 32 + ln;              // band offset 0..63 (1 per lane)
    int col = w_row + jl;               // tile column
    int gj  = jbase + col;
    bool valid = (unsigned)gj < (unsigned)L_;

    // --- score (up to a constant, which cancels in softmax):
    //     acc = sum_d (-2 wa_d) / (1 + 2^(q'_d + k'_d)); 4-way split accumulator
    float a0 = 0.f, a1 = 0.f, a2 = 0.f, a3 = 0.f;
#pragma unroll
    for (int d4 = 0; d4 < D_; d4 += 4) {
        float4 kv = *(const float4*)&ks[col][d4];
        float4 qv = *(const float4*)&qa[w_row][d4];
        float4 wv = *(const float4*)&wa2_s[d4];
        a0 = fmaf(wv.x, sig_m(qv.x + kv.x), a0);
        a1 = fmaf(wv.y, sig_m(qv.y + kv.y), a1);
        a2 = fmaf(wv.z, sig_m(qv.z + kv.z), a2);
        a3 = fmaf(wv.w, sig_m(qv.w + kv.w), a3);
    }
    float acc = (a0 + a1) + (a2 + a3);

    // --- band softmax across 64 entries = 2 warps ---
    float m = valid ? acc : -1e30f;
#pragma unroll
    for (int o = 16; o > 0; o >>= 1) m = fmaxf(m, __shfl_xor_sync(0xffffffffu, m, o));
    if (ln == 0) red_m[w_row][h] = m;
    __syncthreads();
    float M = fmaxf(red_m[w_row][0], red_m[w_row][1]);
    float e = valid ? ex2_m((acc - M) * 1.442695040888963f) : 0.f;
    float s = e;
#pragma unroll
    for (int o = 16; o > 0; o >>= 1) s += __shfl_xor_sync(0xffffffffu, s, o);
    if (ln == 0) red_s[w_row][h] = s;
    __syncthreads();
    float S = red_s[w_row][0] + red_s[w_row][1];
    float a = e * rcp_m(S + 1e-6f);
    qa[w_row][jl] = a;                  // q row dead: reuse as a row
    __syncthreads();

    // --- v[n, c, i]: lane handles c = jl; a via float4 broadcast ---
    int c = jl;
    float vacc = 0.f;
#pragma unroll
    for (int j4 = 0; j4 < 64; j4 += 4) {
        float4 av = *(const float4*)&qa[w_row][j4];
        vacc = fmaf(av.x, xb[c][w_row + j4],     vacc);
        vacc = fmaf(av.y, xb[c][w_row + j4 + 1], vacc);
        vacc = fmaf(av.z, xb[c][w_row + j4 + 2], vacc);
        vacc = fmaf(av.w, xb[c][w_row + j4 + 3], vacc);
    }
    v_s[c][w_row] = vacc;

    // --- full a row, STG.128 (zeros outside band cover the poisoned output) ---
    float* arow = out + (size_t)N_ * C_ * L_ + (size_t)(n * L_ + i) * L_;
#pragma unroll
    for (int k = 0; k < 2; k++) {
        int idx = (h * 64 + k * 32 + ln) << 2;    // float index, multiple of 4
        int j0  = idx - i + 32;
        float4 vv;
        vv.x = ((unsigned)(j0)     < 64u) ? qa[w_row][j0]     : 0.f;
        vv.y = ((unsigned)(j0 + 1) < 64u) ? qa[w_row][j0 + 1] : 0.f;
        vv.z = ((unsigned)(j0 + 2) < 64u) ? qa[w_row][j0 + 2] : 0.f;
        vv.w = ((unsigned)(j0 + 3) < 64u) ? qa[w_row][j0 + 3] : 0.f;
        *(float4*)(arow + idx) = vv;
    }
    __syncthreads();

    // --- coalesced v store via transpose staging ---
    int c2 = t >> 3, il = t & 7;
    out[(n * C_ + c2) * L_ + i0 + il] = v_s[c2][il];
}

// ---------------------------------------------------------------------------
extern "C" void kernel_launch(void* const* d_in, const int* in_sizes, int n_in,
                              void* d_out, int out_size) {
    const float* x  = (const float*)d_in[0];
    const float* Wx = (const float*)d_in[1];
    const float* Wt = (const float*)d_in[2];
    const float* bh = (const float*)d_in[3];
    const float* Wa = (const float*)d_in[4];
    // d_in[5] = ba: cancels inside exp(e - max), unused.
    float* out = (float*)d_out;

    proj_kernel<<<dim3(N_, L_ / 16), 256>>>(x, Wx, Wt, bh);
    band_kernel<<<dim3(N_, L_ / TI), 512>>>(x, Wa, out);
}

// round 8
// speedup vs baseline: 1.5301x; 1.1554x over previous
#include <cuda_runtime.h>

#define N_ 8
#define C_ 64
#define L_ 512
#define D_ 64
#define TI 8     // rows of i per band block
#define KP 68    // ks smem pitch: multiple of 4 (16B align) and conflict-free

// scratch (static device globals — no allocation); 16B-aligned for float4 access
__device__ __align__(16) float g_qb[N_ * L_ * D_];  // q + bh
__device__ __align__(16) float g_kk[N_ * L_ * D_];  // k

// ---------------------------------------------------------------------------
// MUFU ops via inline asm (no fast-math dependence)
// ---------------------------------------------------------------------------
__device__ __forceinline__ float tanh_hw(float z) {
    float y;
    asm("tanh.approx.f32 %0, %1;" : "=f"(y) : "f"(z));
    return y;
}
__device__ __forceinline__ float ex2_m(float z) {
    float y;
    asm("ex2.approx.f32 %0, %1;" : "=f"(y) : "f"(z));
    return y;
}
__device__ __forceinline__ float rcp_m(float den) {
    float y;
    asm("rcp.approx.f32 %0, %1;" : "=f"(y) : "f"(den));
    return y;
}

// ---------------------------------------------------------------------------
// Kernel 1: q = xt@Wt + bh, k = xt@Wx  (raw, no prescale: tanh takes natural arg)
// ---------------------------------------------------------------------------
__global__ void __launch_bounds__(256)
proj_kernel(const float* __restrict__ x,
            const float* __restrict__ Wx,
            const float* __restrict__ Wt,
            const float* __restrict__ bh) {
    __shared__ __align__(16) float wt[C_ * D_];
    __shared__ __align__(16) float wx[C_ * D_];
    __shared__ float xs[C_][17];
    int n  = blockIdx.x;
    int l0 = blockIdx.y * 16;
    int t  = threadIdx.x;

    for (int i4 = t; i4 < C_ * D_ / 4; i4 += 256) {
        ((float4*)wt)[i4] = ((const float4*)Wt)[i4];
        ((float4*)wx)[i4] = ((const float4*)Wx)[i4];
    }
    for (int idx = t; idx < C_ * 16; idx += 256) {
        int c = idx >> 4, ll = idx & 15;
        xs[c][ll] = x[(n * C_ + c) * L_ + l0 + ll];
    }
    __syncthreads();

    int dg = t & 15, ll = t >> 4;
    int d0 = dg << 2;
    float q0 = 0, q1 = 0, q2 = 0, q3 = 0, k0 = 0, k1 = 0, k2 = 0, k3 = 0;
#pragma unroll 8
    for (int c = 0; c < C_; c++) {
        float  xv  = xs[c][ll];
        float4 wt4 = *(const float4*)(wt + c * D_ + d0);
        float4 wx4 = *(const float4*)(wx + c * D_ + d0);
        q0 = fmaf(xv, wt4.x, q0); q1 = fmaf(xv, wt4.y, q1);
        q2 = fmaf(xv, wt4.z, q2); q3 = fmaf(xv, wt4.w, q3);
        k0 = fmaf(xv, wx4.x, k0); k1 = fmaf(xv, wx4.y, k1);
        k2 = fmaf(xv, wx4.z, k2); k3 = fmaf(xv, wx4.w, k3);
    }
    float4 b4 = *(const float4*)(bh + d0);
    int gi = (n * L_ + l0 + ll) * D_ + d0;
    float4 qo = { q0 + b4.x, q1 + b4.y, q2 + b4.z, q3 + b4.w };
    float4 ko = { k0, k1, k2, k3 };
    *(float4*)(g_qb + gi) = qo;
    *(float4*)(g_kk + gi) = ko;
}

// ---------------------------------------------------------------------------
// Kernel 2: banded scores + softmax + a + v. 2 warps per row (one per half-band).
// grid (N_, L_/TI) = 512 blocks, 512 threads = 16 warps. 4 blocks/SM forced.
// ---------------------------------------------------------------------------
__global__ void __launch_bounds__(512, 4)
band_kernel(const float* __restrict__ x,
            const float* __restrict__ Wa,
            float* __restrict__ out) {
    __shared__ __align__(16) float ks[TI + 63][KP];  // k band tile
    __shared__ float xb[C_][71];                     // x band tile (pitch 71)
    __shared__ __align__(16) float qa[TI][64];       // q rows; reused as a rows
    __shared__ __align__(16) float wa_s[D_];         // Wa
    __shared__ float red_s[TI][2];
    __shared__ float v_s[C_][9];                     // v transpose staging

    int n     = blockIdx.x;
    int i0    = blockIdx.y * TI;
    int t     = threadIdx.x;
    int jbase = i0 - 32;

    // --- stage tiles ---
    for (int i4 = t; i4 < (TI + 63) * 16; i4 += 512) {   // k band, float4
        int jj = i4 >> 4, d4 = (i4 & 15) << 2;
        int gj = jbase + jj;
        float4 v = { 0.f, 0.f, 0.f, 0.f };
        if ((unsigned)gj < (unsigned)L_)
            v = *(const float4*)(g_kk + ((n * L_ + gj) << 6) + d4);
        *(float4*)&ks[jj][d4] = v;
    }
    for (int idx = t; idx < C_ * 71; idx += 512) {
        int c = idx / 71, col = idx - c * 71;
        int gj = jbase + col;
        xb[c][col] = ((unsigned)gj < (unsigned)L_) ? x[(n * C_ + c) * L_ + gj] : 0.f;
    }
    if (t < 128) ((float4*)qa)[t] = ((const float4*)(g_qb + (n * L_ + i0) * D_))[t];
    if (t < D_)  wa_s[t] = Wa[t];
    __syncthreads();

    int w = t >> 5, ln = t & 31;
    int w_row = w >> 1, h = w & 1;      // 2 warps per row: h = half-band
    int i   = i0 + w_row;
    int jl  = h * 32 + ln;              // band offset 0..63 (1 per lane)
    int col = w_row + jl;               // tile column
    int gj  = jbase + col;
    bool valid = (unsigned)gj < (unsigned)L_;

    // --- score: acc = sum_d wa_d * tanh(q_d + k_d); 4-way split accumulator ---
    float a0 = 0.f, a1 = 0.f, a2 = 0.f, a3 = 0.f;
#pragma unroll
    for (int d4 = 0; d4 < D_; d4 += 4) {
        float4 kv = *(const float4*)&ks[col][d4];
        float4 qv = *(const float4*)&qa[w_row][d4];
        float4 wv = *(const float4*)&wa_s[d4];
        a0 = fmaf(wv.x, tanh_hw(qv.x + kv.x), a0);
        a1 = fmaf(wv.y, tanh_hw(qv.y + kv.y), a1);
        a2 = fmaf(wv.z, tanh_hw(qv.z + kv.z), a2);
        a3 = fmaf(wv.w, tanh_hw(qv.w + kv.w), a3);
    }
    float acc = (a0 + a1) + (a2 + a3);

    // --- band softmax; no max subtraction (|acc| <= sum|wa| ~ 6, no overflow;
    //     eps-weight difference vs reference is O(1e-8)) ---
    float e = valid ? ex2_m(acc * 1.442695040888963f) : 0.f;
    float s = e;
#pragma unroll
    for (int o = 16; o > 0; o >>= 1) s += __shfl_xor_sync(0xffffffffu, s, o);
    if (ln == 0) red_s[w_row][h] = s;
    __syncthreads();
    float S = red_s[w_row][0] + red_s[w_row][1];
    float a = e * rcp_m(S + 1e-6f);
    qa[w_row][jl] = a;                  // q row dead: reuse as a row
    __syncthreads();

    // --- v[n, c, i]: lane handles c = jl; a via float4 broadcast ---
    int c = jl;
    float vacc = 0.f;
#pragma unroll
    for (int j4 = 0; j4 < 64; j4 += 4) {
        float4 av = *(const float4*)&qa[w_row][j4];
        vacc = fmaf(av.x, xb[c][w_row + j4],     vacc);
        vacc = fmaf(av.y, xb[c][w_row + j4 + 1], vacc);
        vacc = fmaf(av.z, xb[c][w_row + j4 + 2], vacc);
        vacc = fmaf(av.w, xb[c][w_row + j4 + 3], vacc);
    }
    v_s[c][w_row] = vacc;

    // --- full a row, STG.128 (zeros outside band cover the poisoned output) ---
    float* arow = out + (size_t)N_ * C_ * L_ + (size_t)(n * L_ + i) * L_;
#pragma unroll
    for (int k = 0; k < 2; k++) {
        int idx = (h * 64 + k * 32 + ln) << 2;    // float index, multiple of 4
        int j0  = idx - i + 32;
        float4 vv;
        vv.x = ((unsigned)(j0)     < 64u) ? qa[w_row][j0]     : 0.f;
        vv.y = ((unsigned)(j0 + 1) < 64u) ? qa[w_row][j0 + 1] : 0.f;
        vv.z = ((unsigned)(j0 + 2) < 64u) ? qa[w_row][j0 + 2] : 0.f;
        vv.w = ((unsigned)(j0 + 3) < 64u) ? qa[w_row][j0 + 3] : 0.f;
        *(float4*)(arow + idx) = vv;
    }
    __syncthreads();

    // --- coalesced v store via transpose staging ---
    int c2 = t >> 3, il = t & 7;
    out[(n * C_ + c2) * L_ + i0 + il] = v_s[c2][il];
}

// ---------------------------------------------------------------------------
extern "C" void kernel_launch(void* const* d_in, const int* in_sizes, int n_in,
                              void* d_out, int out_size) {
    const float* x  = (const float*)d_in[0];
    const float* Wx = (const float*)d_in[1];
    const float* Wt = (const float*)d_in[2];
    const float* bh = (const float*)d_in[3];
    const float* Wa = (const float*)d_in[4];
    // d_in[5] = ba: cancels in softmax normalization, unused.
    float* out = (float*)d_out;

    proj_kernel<<<dim3(N_, L_ / 16), 256>>>(x, Wx, Wt, bh);
    band_kernel<<<dim3(N_, L_ / TI), 512>>>(x, Wa, out);
}

// round 9
// speedup vs baseline: 1.6366x; 1.0696x over previous
#include <cuda_runtime.h>

#define N_ 8
#define C_ 64
#define L_ 512
#define D_ 64
#define TI 8     // rows of i per band block
#define KP 68    // ks smem pitch: multiple of 4 (16B align) and conflict-free

// scratch (static device globals — no allocation); 16B-aligned for float4 access
__device__ __align__(16) float g_qb[N_ * L_ * D_];  // q + bh
__device__ __align__(16) float g_kk[N_ * L_ * D_];  // k

// pair barrier: 2 warps (64 threads) of one i-row synchronize; ids 1..8
#define PAIR_BAR(id) asm volatile("bar.sync %0, 64;" :: "r"(id) : "memory")

// ---------------------------------------------------------------------------
// MUFU ops via inline asm (no fast-math dependence)
// ---------------------------------------------------------------------------
__device__ __forceinline__ float tanh_hw(float z) {
    float y;
    asm("tanh.approx.f32 %0, %1;" : "=f"(y) : "f"(z));
    return y;
}
__device__ __forceinline__ float ex2_m(float z) {
    float y;
    asm("ex2.approx.f32 %0, %1;" : "=f"(y) : "f"(z));
    return y;
}
__device__ __forceinline__ float rcp_m(float den) {
    float y;
    asm("rcp.approx.f32 %0, %1;" : "=f"(y) : "f"(den));
    return y;
}

// ---------------------------------------------------------------------------
// Kernel 1: q = xt@Wt + bh, k = xt@Wx
// ---------------------------------------------------------------------------
__global__ void __launch_bounds__(256)
proj_kernel(const float* __restrict__ x,
            const float* __restrict__ Wx,
            const float* __restrict__ Wt,
            const float* __restrict__ bh) {
    __shared__ __align__(16) float wt[C_ * D_];
    __shared__ __align__(16) float wx[C_ * D_];
    __shared__ float xs[C_][17];
    int n  = blockIdx.x;
    int l0 = blockIdx.y * 16;
    int t  = threadIdx.x;

    for (int i4 = t; i4 < C_ * D_ / 4; i4 += 256) {
        ((float4*)wt)[i4] = ((const float4*)Wt)[i4];
        ((float4*)wx)[i4] = ((const float4*)Wx)[i4];
    }
    for (int idx = t; idx < C_ * 16; idx += 256) {
        int c = idx >> 4, ll = idx & 15;
        xs[c][ll] = x[(n * C_ + c) * L_ + l0 + ll];
    }
    __syncthreads();

    int dg = t & 15, ll = t >> 4;
    int d0 = dg << 2;
    float q0 = 0, q1 = 0, q2 = 0, q3 = 0, k0 = 0, k1 = 0, k2 = 0, k3 = 0;
#pragma unroll 8
    for (int c = 0; c < C_; c++) {
        float  xv  = xs[c][ll];
        float4 wt4 = *(const float4*)(wt + c * D_ + d0);
        float4 wx4 = *(const float4*)(wx + c * D_ + d0);
        q0 = fmaf(xv, wt4.x, q0); q1 = fmaf(xv, wt4.y, q1);
        q2 = fmaf(xv, wt4.z, q2); q3 = fmaf(xv, wt4.w, q3);
        k0 = fmaf(xv, wx4.x, k0); k1 = fmaf(xv, wx4.y, k1);
        k2 = fmaf(xv, wx4.z, k2); k3 = fmaf(xv, wx4.w, k3);
    }
    float4 b4 = *(const float4*)(bh + d0);
    int gi = (n * L_ + l0 + ll) * D_ + d0;
    float4 qo = { q0 + b4.x, q1 + b4.y, q2 + b4.z, q3 + b4.w };
    float4 ko = { k0, k1, k2, k3 };
    *(float4*)(g_qb + gi) = qo;
    *(float4*)(g_kk + gi) = ko;
}

// ---------------------------------------------------------------------------
// Kernel 2: banded scores + softmax + a + v. 2 warps per row (one per half-band).
// grid (N_, L_/TI) = 512 blocks, 512 threads = 16 warps. 4 blocks/SM.
// Mid-kernel syncs are per-pair named barriers, not block-wide.
// ---------------------------------------------------------------------------
__global__ void __launch_bounds__(512, 4)
band_kernel(const float* __restrict__ x,
            const float* __restrict__ Wa,
            float* __restrict__ out) {
    __shared__ __align__(16) float ks[TI + 63][KP];  // k band tile
    __shared__ float xb[C_][71];                     // x band tile (pitch 71)
    __shared__ __align__(16) float qa[TI][64];       // q rows; reused as a rows
    __shared__ __align__(16) float wa_s[D_];         // Wa
    __shared__ float red_s[TI][2];
    __shared__ float v_s[C_][9];                     // v transpose staging

    int n     = blockIdx.x;
    int i0    = blockIdx.y * TI;
    int t     = threadIdx.x;
    int jbase = i0 - 32;

    // --- stage tiles ---
    for (int i4 = t; i4 < (TI + 63) * 16; i4 += 512) {   // k band, float4
        int jj = i4 >> 4, d4 = (i4 & 15) << 2;
        int gj = jbase + jj;
        float4 v = { 0.f, 0.f, 0.f, 0.f };
        if ((unsigned)gj < (unsigned)L_)
            v = *(const float4*)(g_kk + ((n * L_ + gj) << 6) + d4);
        *(float4*)&ks[jj][d4] = v;
    }
    {   // x band: t -> (c = t>>3, cols (t&7) + 8k), no integer division
        int c = t >> 3, cb = t & 7;
        const float* xrow = x + (n * C_ + c) * L_;
#pragma unroll
        for (int k = 0; k < 9; k++) {
            int col = cb + (k << 3);
            if (col < 71) {
                int gj = jbase + col;
                xb[c][col] = ((unsigned)gj < (unsigned)L_) ? xrow[gj] : 0.f;
            }
        }
    }
    if (t < 128) ((float4*)qa)[t] = ((const float4*)(g_qb + (n * L_ + i0) * D_))[t];
    if (t < D_)  wa_s[t] = Wa[t];
    __syncthreads();

    int w = t >> 5, ln = t & 31;
    int w_row = w >> 1, h = w & 1;      // 2 warps per row: h = half-band
    int bar_id = 1 + w_row;             // named barrier per row pair
    int i   = i0 + w_row;
    int jl  = h * 32 + ln;              // band offset 0..63 (1 per lane)
    int col = w_row + jl;               // tile column
    int gj  = jbase + col;
    bool valid = (unsigned)gj < (unsigned)L_;

    // --- score: acc = sum_d wa_d * tanh(q_d + k_d); 4-way split accumulator ---
    const float* ksr = &ks[col][0];
    const float* qar = &qa[w_row][0];
    float a0 = 0.f, a1 = 0.f, a2 = 0.f, a3 = 0.f;
#pragma unroll
    for (int d4 = 0; d4 < D_; d4 += 4) {
        float4 kv = *(const float4*)(ksr + d4);
        float4 qv = *(const float4*)(qar + d4);
        float4 wv = *(const float4*)(wa_s + d4);
        a0 = fmaf(wv.x, tanh_hw(qv.x + kv.x), a0);
        a1 = fmaf(wv.y, tanh_hw(qv.y + kv.y), a1);
        a2 = fmaf(wv.z, tanh_hw(qv.z + kv.z), a2);
        a3 = fmaf(wv.w, tanh_hw(qv.w + kv.w), a3);
    }
    float acc = (a0 + a1) + (a2 + a3);

    // --- band softmax; no max subtraction (|acc| <= sum|wa| ~ 6, no overflow;
    //     eps-weight difference vs reference is O(1e-8)) ---
    float e = valid ? ex2_m(acc * 1.442695040888963f) : 0.f;
    float s = e;
#pragma unroll
    for (int o = 16; o > 0; o >>= 1) s += __shfl_xor_sync(0xffffffffu, s, o);
    if (ln == 0) red_s[w_row][h] = s;
    PAIR_BAR(bar_id);
    float S = red_s[w_row][0] + red_s[w_row][1];
    float a = e * rcp_m(S + 1e-6f);
    qa[w_row][jl] = a;                  // q row dead: reuse as a row
    PAIR_BAR(bar_id);

    // --- v[n, c, i]: lane handles c = jl; a via float4 broadcast ---
    int c = jl;
    float vacc = 0.f;
#pragma unroll
    for (int j4 = 0; j4 < 64; j4 += 4) {
        float4 av = *(const float4*)(qar + j4);
        vacc = fmaf(av.x, xb[c][w_row + j4],     vacc);
        vacc = fmaf(av.y, xb[c][w_row + j4 + 1], vacc);
        vacc = fmaf(av.z, xb[c][w_row + j4 + 2], vacc);
        vacc = fmaf(av.w, xb[c][w_row + j4 + 3], vacc);
    }
    v_s[c][w_row] = vacc;

    // --- full a row, STG.128 (zeros outside band cover the poisoned output) ---
    float* arow = out + (size_t)N_ * C_ * L_ + (size_t)(n * L_ + i) * L_;
#pragma unroll
    for (int k = 0; k < 2; k++) {
        int idx = (h * 64 + k * 32 + ln) << 2;    // float index, multiple of 4
        int j0  = idx - i + 32;
        float4 vv;
        vv.x = ((unsigned)(j0)     < 64u) ? qa[w_row][j0]     : 0.f;
        vv.y = ((unsigned)(j0 + 1) < 64u) ? qa[w_row][j0 + 1] : 0.f;
        vv.z = ((unsigned)(j0 + 2) < 64u) ? qa[w_row][j0 + 2] : 0.f;
        vv.w = ((unsigned)(j0 + 3) < 64u) ? qa[w_row][j0 + 3] : 0.f;
        *(float4*)(arow + idx) = vv;
    }
    __syncthreads();   // all pairs' v_s ready

    // --- coalesced v store via transpose staging ---
    int c2 = t >> 3, il = t & 7;
    out[(n * C_ + c2) * L_ + i0 + il] = v_s[c2][il];
}

// ---------------------------------------------------------------------------
extern "C" void kernel_launch(void* const* d_in, const int* in_sizes, int n_in,
                              void* d_out, int out_size) {
    const float* x  = (const float*)d_in[0];
    const float* Wx = (const float*)d_in[1];
    const float* Wt = (const float*)d_in[2];
    const float* bh = (const float*)d_in[3];
    const float* Wa = (const float*)d_in[4];
    // d_in[5] = ba: cancels in softmax normalization, unused.
    float* out = (float*)d_out;

    proj_kernel<<<dim3(N_, L_ / 16), 256>>>(x, Wx, Wt, bh);
    band_kernel<<<dim3(N_, L_ / TI), 512>>>(x, Wa, out);
}